// round 14
// baseline (speedup 1.0000x reference)
#include <cuda_runtime.h>
#include <cuda_fp16.h>
#include <cstdint>

#define KDIM   65536
#define MROWS  2048
#define NDFv   256
#define NCv    100
#define KC     64
#define NCTAS  148
#define TOTAL_UNITS 32768        // 32 mn-tiles * 1024 chunks
#define OFF_AH 0
#define OFF_AS 16384
#define OFF_BH 32768
#define OFF_BS 49152
#define STAGE  65536
#define NSTAGES 3
#define SMEM_TOTAL (NSTAGES * STAGE)   // 192 KB

#define NTHREADS 320             // 256 consumers + 64 producers
#define KAPPA_INV 32.0f
#define ONE_MK    0.96875f       // 1 - 2^-5

// device-global scratch (no cudaMalloc allowed)
__device__ __align__(16) unsigned short g_Bh[(size_t)NDFv * KDIM]; // [n][k] fp16 rn(w)
__device__ __align__(16) unsigned short g_Bs[(size_t)NDFv * KDIM]; // [n][k] fp16 Bh+32*Bl
__device__ float g_partial[(size_t)2 * NCTAS * 16384];             // [cta*2+seg][128*128]

// ---------------- helpers (sm_80-class PTX only: valid on compute_103) ------
__device__ __forceinline__ uint32_t smem_u32(const void* p) {
    uint32_t a;
    asm("{ .reg .u64 t; cvta.to.shared.u64 t, %1; cvt.u32.u64 %0, t; }" : "=r"(a) : "l"(p));
    return a;
}
__device__ __forceinline__ uint32_t packh2(float lo, float hi) { // low half = rn16(lo)
    uint32_t r;
    asm("cvt.rn.f16x2.f32 %0, %1, %2;" : "=r"(r) : "f"(hi), "f"(lo));
    return r;
}
#define STS64V(a, r0, r1) \
    asm volatile("st.shared.v2.b32 [%0], {%1,%2};" :: "r"(a), "r"(r0), "r"(r1) : "memory")
#define CP_ASYNC16(dst, src) \
    asm volatile("cp.async.cg.shared.global [%0], [%1], 16;" :: "r"(dst), "l"(src) : "memory")
#define CP_COMMIT() asm volatile("cp.async.commit_group;" ::: "memory")
#define CP_WAIT0()  asm volatile("cp.async.wait_group 0;" ::: "memory")
#define MEMBAR_CTA() asm volatile("membar.cta;" ::: "memory")
#define BAR_SYNC(id)   asm volatile("bar.sync %0, %1;"   :: "r"(id), "r"(NTHREADS) : "memory")
#define BAR_ARRIVE(id) asm volatile("bar.arrive %0, %1;" :: "r"(id), "r"(NTHREADS) : "memory")
// barrier ids: 1+s = stage s FULL, 4+s = stage s EMPTY

__device__ __forceinline__ void ldsm4(uint32_t r[4], uint32_t a) {
    asm volatile("ldmatrix.sync.aligned.m8n8.x4.shared.b16 {%0,%1,%2,%3}, [%4];"
                 : "=r"(r[0]), "=r"(r[1]), "=r"(r[2]), "=r"(r[3]) : "r"(a));
}
__device__ __forceinline__ void mmaf16(float d[4], const uint32_t a[4],
                                       uint32_t b0, uint32_t b1) {
    asm volatile("mma.sync.aligned.m16n8k16.row.col.f32.f16.f16.f32 "
                 "{%0,%1,%2,%3},{%4,%5,%6,%7},{%8,%9},{%0,%1,%2,%3};"
                 : "+f"(d[0]), "+f"(d[1]), "+f"(d[2]), "+f"(d[3])
                 : "r"(a[0]), "r"(a[1]), "r"(a[2]), "r"(a[3]), "r"(b0), "r"(b1));
}

// ---------------- prepass: W [K,256] fp32 -> g_Bh/g_Bs [256][K] fp16 --------
__global__ __launch_bounds__(256) void bprep_kernel(const float* __restrict__ W) {
    __shared__ float tile[32][33];
    const int k0 = blockIdx.x * 32, n0 = blockIdx.y * 32;
    const int tx = threadIdx.x & 31, ty = threadIdx.x >> 5;
    #pragma unroll
    for (int i = 0; i < 4; i++)
        tile[ty * 4 + i][tx] = W[(size_t)(k0 + ty * 4 + i) * NDFv + n0 + tx];
    __syncthreads();
    #pragma unroll
    for (int i = 0; i < 4; i++) {
        const int n = ty * 4 + i;
        const float w = tile[tx][n];
        const __half bh = __float2half_rn(w);
        const float bhf = __half2float(bh);
        const float bl = w - bhf;
        const __half bs = __float2half_rn(fmaf(KAPPA_INV, bl, bhf));
        const size_t idx = (size_t)(n0 + n) * KDIM + k0 + tx;
        g_Bh[idx] = *(const unsigned short*)&bh;
        g_Bs[idx] = *(const unsigned short*)&bs;
    }
}

// ---------------- GEMM: fp16 2-pass kappa split, persistent, 3 stages -------
__global__ __launch_bounds__(NTHREADS, 1) void gemm_mma_kernel(const float* __restrict__ A) {
    extern __shared__ char smem_dyn[];
    const uint32_t sbase = smem_u32(smem_dyn);
    const int tid = threadIdx.x;
    const int cta = blockIdx.x;
    const int u_begin = (cta * TOTAL_UNITS) / NCTAS;
    const int u_end   = ((cta + 1) * TOTAL_UNITS) / NCTAS;
    const int total   = u_end - u_begin;

    if (tid >= 256) {
        // ================= PRODUCER (warps 8-9, 64 threads) =================
        const int pt = tid - 256;             // 0..63
        const int prow = pt >> 4;             // A: row offset within group of 4
        const int pkf4 = pt & 15;             // A: float4 index within row
        const int prow8 = pt >> 3;            // B: row offset within group of 8
        const int pseg = pt & 7;              // B: 16B segment within row

        float4 bufA[8], bufB[8];

#define PLDG(buf, Ab, b) do {                                                    \
    _Pragma("unroll")                                                            \
    for (int j = 0; j < 8; j++) {                                                \
        const int row = (b) * 32 + j * 4 + prow;                                 \
        (buf)[j] = *(const float4*)((Ab) + (size_t)row * KDIM);                  \
    } } while (0)

#define PSTS(buf, st, b) do {                                                    \
    _Pragma("unroll")                                                            \
    for (int j = 0; j < 8; j++) {                                                \
        const int row = (b) * 32 + j * 4 + prow;                                 \
        const uint32_t off = (uint32_t)(row * 128) +                             \
                             (((uint32_t)(pkf4 * 8)) ^ ((uint32_t)((row & 7) << 4))); \
        const float4 f = (buf)[j];                                               \
        const uint32_t h0 = packh2(f.x, f.y);                                    \
        const uint32_t h1 = packh2(f.z, f.w);                                    \
        const float ahx = __half2float(*(const __half*)&h0);                     \
        const float ahy = __half2float(((const __half*)&h0)[1]);                 \
        const float ahz = __half2float(*(const __half*)&h1);                     \
        const float ahw = __half2float(((const __half*)&h1)[1]);                 \
        const uint32_t s0 = packh2(fmaf(-ONE_MK, ahx, f.x), fmaf(-ONE_MK, ahy, f.y)); \
        const uint32_t s1 = packh2(fmaf(-ONE_MK, ahz, f.z), fmaf(-ONE_MK, ahw, f.w)); \
        STS64V((st) + OFF_AH + off, h0, h1);                                     \
        STS64V((st) + OFF_AS + off, s0, s1);                                     \
    } } while (0)

        int s = 0;
        for (int it = 0; it < total; it++) {
            const uint32_t st = sbase + (uint32_t)(s * STAGE);
            if (it >= NSTAGES) BAR_SYNC(4 + s);  // wait stage empty

            const int u  = u_begin + it;
            const int mt = u >> 11;              // tile>>1
            const int nt = (u >> 10) & 1;
            const int ch = u & 1023;

            // B -> cp.async (fills while we convert A)
            {
                const unsigned short* bh = g_Bh + (size_t)(nt * 128) * KDIM
                                           + (size_t)ch * KC + pseg * 8;
                const unsigned short* bs = g_Bs + (size_t)(nt * 128) * KDIM
                                           + (size_t)ch * KC + pseg * 8;
                #pragma unroll
                for (int j = 0; j < 16; j++) {
                    const int row = j * 8 + prow8;
                    const uint32_t off = (uint32_t)(row * 128) +
                        (((uint32_t)(pseg * 16)) ^ ((uint32_t)(prow8 << 4)));
                    CP_ASYNC16(st + OFF_BH + off, bh + (size_t)row * KDIM);
                    CP_ASYNC16(st + OFF_BS + off, bs + (size_t)row * KDIM);
                }
                CP_COMMIT();
            }
            // A: 4 batches, reg double-buffered
            const float* Ab = A + (size_t)(mt * 128) * KDIM + (size_t)ch * KC
                              + pkf4 * 4;
            PLDG(bufA, Ab, 0);
            PLDG(bufB, Ab, 1);
            PSTS(bufA, st, 0);
            PLDG(bufA, Ab, 2);
            PSTS(bufB, st, 1);
            PLDG(bufB, Ab, 3);
            PSTS(bufA, st, 2);
            PSTS(bufB, st, 3);
            CP_WAIT0();
            MEMBAR_CTA();
            BAR_ARRIVE(1 + s);                   // publish stage full
            if (++s == NSTAGES) s = 0;
        }
        return;
    }

    // ================= CONSUMERS (warps 0-7, 256 threads) ===================
    const int wid = tid >> 5, lane = tid & 31;
    const int wm = wid & 1, wn = wid >> 1;       // warp tile: m64 x n32

    const int a_r = (lane & 7) + ((lane >> 3) & 1) * 8;
    const uint32_t a_c16 = (uint32_t)(((lane >> 4) & 1) * 16);
    const uint32_t xf = (uint32_t)((a_r & 7) << 4);
    uint32_t colx[4];
    #pragma unroll
    for (int ks = 0; ks < 4; ks++) colx[ks] = (((uint32_t)ks << 5) | a_c16) ^ xf;

    float acc1[4][4][4] = {};   // P1 = Ah*Bh
    float acc2[4][4][4] = {};   // P2 = As*Bs
    int slot = cta * 2;

#define KSTEP(ks) do {                                                           \
    uint32_t ah[4][4], bh[2][4];                                                 \
    _Pragma("unroll")                                                            \
    for (int mf = 0; mf < 4; mf++)                                               \
        ldsm4(ah[mf], st + OFF_AH + (uint32_t)((wm * 64 + mf * 16 + a_r) * 128) + colx[ks]); \
    _Pragma("unroll")                                                            \
    for (int g = 0; g < 2; g++)                                                  \
        ldsm4(bh[g], st + OFF_BH + (uint32_t)((wn * 32 + g * 16 + a_r) * 128) + colx[ks]);   \
    _Pragma("unroll")                                                            \
    for (int mf = 0; mf < 4; mf++)                                               \
        _Pragma("unroll")                                                        \
        for (int g = 0; g < 2; g++) {                                            \
            mmaf16(acc1[mf][g * 2 + 0], ah[mf], bh[g][0], bh[g][2]);             \
            mmaf16(acc1[mf][g * 2 + 1], ah[mf], bh[g][1], bh[g][3]);             \
        }                                                                        \
    uint32_t as[4][4], bs[2][4];                                                 \
    _Pragma("unroll")                                                            \
    for (int mf = 0; mf < 4; mf++)                                               \
        ldsm4(as[mf], st + OFF_AS + (uint32_t)((wm * 64 + mf * 16 + a_r) * 128) + colx[ks]); \
    _Pragma("unroll")                                                            \
    for (int g = 0; g < 2; g++)                                                  \
        ldsm4(bs[g], st + OFF_BS + (uint32_t)((wn * 32 + g * 16 + a_r) * 128) + colx[ks]);   \
    _Pragma("unroll")                                                            \
    for (int mf = 0; mf < 4; mf++)                                               \
        _Pragma("unroll")                                                        \
        for (int g = 0; g < 2; g++) {                                            \
            mmaf16(acc2[mf][g * 2 + 0], as[mf], bs[g][0], bs[g][2]);             \
            mmaf16(acc2[mf][g * 2 + 1], as[mf], bs[g][1], bs[g][3]);             \
        } } while (0)

    int s = 0;
    for (int it = 0; it < total; it++) {
        const uint32_t st = sbase + (uint32_t)(s * STAGE);
        BAR_SYNC(1 + s);                 // wait stage full
        KSTEP(0);
        KSTEP(1);
        KSTEP(2);
        KSTEP(3);
        if (it + NSTAGES < total) BAR_ARRIVE(4 + s);   // signal stage empty
        if (++s == NSTAGES) s = 0;

        const int u = u_begin + it;
        if (it == total - 1 || ((u + 1) & 1023) == 0) {
            // tile segment done: flush to slot, reset accumulators
            float* pb = g_partial + (size_t)slot * 16384;
            #pragma unroll
            for (int mf = 0; mf < 4; mf++)
                #pragma unroll
                for (int nf = 0; nf < 4; nf++) {
                    const int rl = wm * 64 + mf * 16 + (lane >> 2);
                    const int cl = wn * 32 + nf * 8 + (lane & 3) * 2;
                    const float v0 = fmaf(ONE_MK, acc1[mf][nf][0], acc2[mf][nf][0]);
                    const float v1 = fmaf(ONE_MK, acc1[mf][nf][1], acc2[mf][nf][1]);
                    const float v2 = fmaf(ONE_MK, acc1[mf][nf][2], acc2[mf][nf][2]);
                    const float v3 = fmaf(ONE_MK, acc1[mf][nf][3], acc2[mf][nf][3]);
                    *(float2*)(pb + rl * 128 + cl) = make_float2(v0, v1);
                    *(float2*)(pb + (rl + 8) * 128 + cl) = make_float2(v2, v3);
                    acc1[mf][nf][0] = acc1[mf][nf][1] = acc1[mf][nf][2] = acc1[mf][nf][3] = 0.f;
                    acc2[mf][nf][0] = acc2[mf][nf][1] = acc2[mf][nf][2] = acc2[mf][nf][3] = 0.f;
                }
            slot++;
        }
    }
}

// ---------------- fused: split-K reduce + bias/mask + student-t + argmax ----
// One block per 8 rows. Reconstructs zall rows from g_partial (same summation
// order as the old reduce kernel -> bitwise identical), writes zall, then
// computes s and c from the smem copy.
__global__ __launch_bounds__(128) void cluster_kernel(const float* __restrict__ bias,
                                                      const int* __restrict__ mask,
                                                      const float* __restrict__ cent,
                                                      float* __restrict__ zall,
                                                      float* __restrict__ S,
                                                      float* __restrict__ Cidx) {
    const int tid = threadIdx.x;
    const int row0 = blockIdx.x * 8;
    __shared__ __align__(16) float zs[8][256];
    __shared__ float stmp[8][128];
    __shared__ float red_s[8];
    __shared__ int   red_i[8];
    __shared__ int   slots[2][8];
    __shared__ int   nslots[2];

    // contributor lists for this row-block's two mn-tiles
    if (tid == 0) {
        const int tbase = (row0 >> 7) << 1;
        #pragma unroll
        for (int h = 0; h < 2; h++) {
            const int t = tbase + h;
            int n = 0;
            int c0 = (t << 10) * NCTAS / TOTAL_UNITS - 1;
            if (c0 < 0) c0 = 0;
            for (int c = c0; c < c0 + 8 && c < NCTAS; c++) {
                const int u0 = (c * TOTAL_UNITS) / NCTAS;
                const int u1 = ((c + 1) * TOTAL_UNITS) / NCTAS;
                if (u0 < ((t + 1) << 10) && u1 > (t << 10))
                    slots[h][n++] = c * 2 + (((u0 >> 10) == t) ? 0 : 1);
            }
            nslots[h] = n;
        }
    }
    __syncthreads();

    // reduce: thread tid handles float2 column tid*2 across 8 rows
    {
        const int col = tid * 2;
        const int h = col >> 7;          // which tile half
        const int cl = col & 127;
        const int nct = nslots[h];
        const float bx = bias[col], by = bias[col + 1];
        #pragma unroll
        for (int r = 0; r < 8; r++) {
            const int row = row0 + r;
            const int rl = row & 127;
            float sx = 0.f, sy = 0.f;
            for (int i = 0; i < nct; i++) {
                const float2 v = *(const float2*)(g_partial +
                    (size_t)slots[h][i] * 16384 + rl * 128 + cl);
                sx += v.x; sy += v.y;
            }
            const float m = mask[row] ? 1.0f : 0.0f;
            sx = (sx + bx) * m;
            sy = (sy + by) * m;
            zs[r][col] = sx;
            zs[r][col + 1] = sy;
            *(float2*)&zall[(size_t)row * NDFv + col] = make_float2(sx, sy);
        }
    }
    __syncthreads();

    float v[8] = {0.f, 0.f, 0.f, 0.f, 0.f, 0.f, 0.f, 0.f};
    if (tid < NCv) {
        const float4* c4 = (const float4*)(cent + (size_t)tid * NDFv);
        float d[8] = {0.f, 0.f, 0.f, 0.f, 0.f, 0.f, 0.f, 0.f};
        #pragma unroll 2
        for (int j = 0; j < NDFv / 4; j++) {
            const float4 cv = c4[j];
            #pragma unroll
            for (int r = 0; r < 8; r++) {
                const float4 zv = ((const float4*)zs[r])[j];
                const float dx = zv.x - cv.x, dy = zv.y - cv.y;
                const float dz = zv.z - cv.z, dw = zv.w - cv.w;
                d[r] += dx * dx + dy * dy + dz * dz + dw * dw;
            }
        }
        #pragma unroll
        for (int r = 0; r < 8; r++)
            v[r] = 1.0f / (1.0f + sqrtf(fmaxf(d[r], 0.0f)));
    }
    #pragma unroll
    for (int r = 0; r < 8; r++) stmp[r][tid] = v[r];
    __syncthreads();

    #pragma unroll
    for (int pass = 0; pass < 2; pass++) {   // warp w reduces rows w and w+4
        const int r = (tid >> 5) + pass * 4;
        const int l = tid & 31;
        float sum = 0.0f, best = -1.0f;
        int bidx = 0;
        for (int k = l; k < NCv; k += 32) {
            const float x = stmp[r][k];
            sum += x;
            if (x > best) { best = x; bidx = k; }
        }
        #pragma unroll
        for (int off = 16; off > 0; off >>= 1) {
            sum += __shfl_down_sync(0xffffffffu, sum, off);
            const float ob = __shfl_down_sync(0xffffffffu, best, off);
            const int   oi = __shfl_down_sync(0xffffffffu, bidx, off);
            if (ob > best || (ob == best && oi < bidx)) { best = ob; bidx = oi; }
        }
        if (l == 0) { red_s[r] = sum; red_i[r] = bidx; }
    }
    __syncthreads();

    #pragma unroll
    for (int r = 0; r < 8; r++) {
        const int row = row0 + r;
        const bool m = mask[row] != 0;
        const float inv = m ? (1.0f / red_s[r]) : 0.0f;
        if (tid < NCv) S[(size_t)row * NCv + tid] = v[r] * inv;
        if (tid == 0)  Cidx[row] = m ? (float)red_i[r] : 0.0f;
    }
}

// ---------------------------------------------------------------------------
extern "C" void kernel_launch(void* const* d_in, const int* in_sizes, int n_in,
                              void* d_out, int out_size) {
    (void)in_sizes; (void)n_in; (void)out_size;
    const float* z_roi = (const float*)d_in[0];
    const int*   mask  = (const int*)d_in[1];
    const float* w_emb = (const float*)d_in[2];
    const float* b_emb = (const float*)d_in[3];
    const float* cent  = (const float*)d_in[4];

    float* out  = (float*)d_out;
    float* zall = out;
    float* S    = out + (size_t)MROWS * NDFv;
    float* Cx   = S + (size_t)MROWS * NCv;

    cudaFuncSetAttribute(gemm_mma_kernel, cudaFuncAttributeMaxDynamicSharedMemorySize, SMEM_TOTAL);

    bprep_kernel<<<dim3(KDIM / 32, NDFv / 32), 256>>>(w_emb);
    gemm_mma_kernel<<<NCTAS, NTHREADS, SMEM_TOTAL>>>(z_roi);
    cluster_kernel<<<MROWS / 8, 128>>>(b_emb, mask, cent, zall, S, Cx);
}

// round 15
// speedup vs baseline: 1.0047x; 1.0047x over previous
#include <cuda_runtime.h>
#include <cuda_fp16.h>
#include <cstdint>

#define KDIM   65536
#define MROWS  2048
#define NDFv   256
#define NCv    100
#define KC     64
#define NCTAS  148
#define TOTAL_UNITS 32768        // 32 mn-tiles * 1024 chunks
#define OFF_AH 0
#define OFF_AS 16384
#define OFF_BH 32768
#define OFF_BS 49152
#define STAGE  65536
#define SMEM_TOTAL (2 * STAGE)   // 128 KB

#define NTHREADS 320             // 256 consumers + 64 producers
#define KAPPA_INV 32.0f
#define ONE_MK    0.96875f       // 1 - 2^-5

// device-global scratch (no cudaMalloc allowed)
__device__ __align__(16) unsigned short g_Bh[(size_t)NDFv * KDIM]; // [n][k] fp16 rn(w)
__device__ __align__(16) unsigned short g_Bs[(size_t)NDFv * KDIM]; // [n][k] fp16 Bh+32*Bl
__device__ float g_partial[(size_t)2 * NCTAS * 16384];             // [cta*2+seg][128*128]

// ---------------- helpers (sm_80-class PTX only: valid on compute_103) ------
__device__ __forceinline__ uint32_t smem_u32(const void* p) {
    uint32_t a;
    asm("{ .reg .u64 t; cvta.to.shared.u64 t, %1; cvt.u32.u64 %0, t; }" : "=r"(a) : "l"(p));
    return a;
}
__device__ __forceinline__ uint32_t packh2(float lo, float hi) { // low half = rn16(lo)
    uint32_t r;
    asm("cvt.rn.f16x2.f32 %0, %1, %2;" : "=r"(r) : "f"(hi), "f"(lo));
    return r;
}
#define STS64V(a, r0, r1) \
    asm volatile("st.shared.v2.b32 [%0], {%1,%2};" :: "r"(a), "r"(r0), "r"(r1) : "memory")
#define CP_ASYNC16(dst, src) \
    asm volatile("cp.async.cg.shared.global [%0], [%1], 16;" :: "r"(dst), "l"(src) : "memory")
#define CP_COMMIT() asm volatile("cp.async.commit_group;" ::: "memory")
#define CP_WAIT0()  asm volatile("cp.async.wait_group 0;" ::: "memory")
#define MEMBAR_CTA() asm volatile("membar.cta;" ::: "memory")
#define BAR_SYNC(id)   asm volatile("bar.sync %0, %1;"   :: "r"(id), "r"(NTHREADS) : "memory")
#define BAR_ARRIVE(id) asm volatile("bar.arrive %0, %1;" :: "r"(id), "r"(NTHREADS) : "memory")
// barrier ids: 1+s = stage s FULL, 3+s = stage s EMPTY

__device__ __forceinline__ void ldsm4(uint32_t r[4], uint32_t a) {
    asm volatile("ldmatrix.sync.aligned.m8n8.x4.shared.b16 {%0,%1,%2,%3}, [%4];"
                 : "=r"(r[0]), "=r"(r[1]), "=r"(r[2]), "=r"(r[3]) : "r"(a));
}
__device__ __forceinline__ void mmaf16(float d[4], const uint32_t a[4],
                                       uint32_t b0, uint32_t b1) {
    asm volatile("mma.sync.aligned.m16n8k16.row.col.f32.f16.f16.f32 "
                 "{%0,%1,%2,%3},{%4,%5,%6,%7},{%8,%9},{%0,%1,%2,%3};"
                 : "+f"(d[0]), "+f"(d[1]), "+f"(d[2]), "+f"(d[3])
                 : "r"(a[0]), "r"(a[1]), "r"(a[2]), "r"(a[3]), "r"(b0), "r"(b1));
}

// ---------------- prepass: W [K,256] fp32 -> g_Bh/g_Bs [256][K] fp16 --------
// Write phase emits packed uint32 (2 x fp16) stores; per-element math identical.
__global__ __launch_bounds__(256) void bprep_kernel(const float* __restrict__ W) {
    __shared__ float tile[32][33];
    const int k0 = blockIdx.x * 32, n0 = blockIdx.y * 32;
    const int tx = threadIdx.x & 31, ty = threadIdx.x >> 5;
    #pragma unroll
    for (int i = 0; i < 4; i++)
        tile[ty * 4 + i][tx] = W[(size_t)(k0 + ty * 4 + i) * NDFv + n0 + tx];
    __syncthreads();
    const int kp = (tx & 15) * 2;        // k pair base
    const int nh = (tx >> 4) * 2;        // n subgroup (0 or 2)
    #pragma unroll
    for (int i2 = 0; i2 < 2; i2++) {
        const int nl = ty * 4 + nh + i2;
        const float w0 = tile[kp][nl];
        const float w1 = tile[kp + 1][nl];
        const uint32_t hp = packh2(w0, w1);
        const float bhf0 = __half2float(*(const __half*)&hp);
        const float bhf1 = __half2float(((const __half*)&hp)[1]);
        const uint32_t sp = packh2(fmaf(KAPPA_INV, w0 - bhf0, bhf0),
                                   fmaf(KAPPA_INV, w1 - bhf1, bhf1));
        const size_t idx = (size_t)(n0 + nl) * KDIM + k0 + kp;
        *(uint32_t*)&g_Bh[idx] = hp;
        *(uint32_t*)&g_Bs[idx] = sp;
    }
}

// ---------------- GEMM: fp16 2-pass kappa split, persistent balanced --------
__global__ __launch_bounds__(NTHREADS, 1) void gemm_mma_kernel(const float* __restrict__ A) {
    extern __shared__ char smem_dyn[];
    const uint32_t sbase = smem_u32(smem_dyn);
    const int tid = threadIdx.x;
    const int cta = blockIdx.x;
    const int u_begin = (cta * TOTAL_UNITS) / NCTAS;
    const int u_end   = ((cta + 1) * TOTAL_UNITS) / NCTAS;
    const int total   = u_end - u_begin;

    if (tid >= 256) {
        // ================= PRODUCER (warps 8-9, 64 threads) =================
        const int pt = tid - 256;             // 0..63
        const int prow = pt >> 4;             // A: row offset within group of 4
        const int pkf4 = pt & 15;             // A: float4 index within row
        const int prow8 = pt >> 3;            // B: row offset within group of 8
        const int pseg = pt & 7;              // B: 16B segment within row

        float4 bufA[8], bufB[8];

#define PLDG(buf, Ab, b) do {                                                    \
    _Pragma("unroll")                                                            \
    for (int j = 0; j < 8; j++) {                                                \
        const int row = (b) * 32 + j * 4 + prow;                                 \
        (buf)[j] = *(const float4*)((Ab) + (size_t)row * KDIM);                  \
    } } while (0)

#define PSTS(buf, st, b) do {                                                    \
    _Pragma("unroll")                                                            \
    for (int j = 0; j < 8; j++) {                                                \
        const int row = (b) * 32 + j * 4 + prow;                                 \
        const uint32_t off = (uint32_t)(row * 128) +                             \
                             (((uint32_t)(pkf4 * 8)) ^ ((uint32_t)((row & 7) << 4))); \
        const float4 f = (buf)[j];                                               \
        const uint32_t h0 = packh2(f.x, f.y);                                    \
        const uint32_t h1 = packh2(f.z, f.w);                                    \
        const float ahx = __half2float(*(const __half*)&h0);                     \
        const float ahy = __half2float(((const __half*)&h0)[1]);                 \
        const float ahz = __half2float(*(const __half*)&h1);                     \
        const float ahw = __half2float(((const __half*)&h1)[1]);                 \
        const uint32_t s0 = packh2(fmaf(-ONE_MK, ahx, f.x), fmaf(-ONE_MK, ahy, f.y)); \
        const uint32_t s1 = packh2(fmaf(-ONE_MK, ahz, f.z), fmaf(-ONE_MK, ahw, f.w)); \
        STS64V((st) + OFF_AH + off, h0, h1);                                     \
        STS64V((st) + OFF_AS + off, s0, s1);                                     \
    } } while (0)

        for (int it = 0; it < total; it++) {
            const int s = it & 1;
            const uint32_t st = sbase + (uint32_t)(s * STAGE);
            if (it >= 2) BAR_SYNC(3 + s);        // wait stage empty

            const int u  = u_begin + it;
            const int mt = u >> 11;              // tile>>1
            const int nt = (u >> 10) & 1;
            const int ch = u & 1023;

            // B -> cp.async (fills while we convert A)
            {
                const unsigned short* bh = g_Bh + (size_t)(nt * 128) * KDIM
                                           + (size_t)ch * KC + pseg * 8;
                const unsigned short* bs = g_Bs + (size_t)(nt * 128) * KDIM
                                           + (size_t)ch * KC + pseg * 8;
                #pragma unroll
                for (int j = 0; j < 16; j++) {
                    const int row = j * 8 + prow8;
                    const uint32_t off = (uint32_t)(row * 128) +
                        (((uint32_t)(pseg * 16)) ^ ((uint32_t)(prow8 << 4)));
                    CP_ASYNC16(st + OFF_BH + off, bh + (size_t)row * KDIM);
                    CP_ASYNC16(st + OFF_BS + off, bs + (size_t)row * KDIM);
                }
                CP_COMMIT();
            }
            // A: 4 batches, reg double-buffered
            const float* Ab = A + (size_t)(mt * 128) * KDIM + (size_t)ch * KC
                              + pkf4 * 4;
            PLDG(bufA, Ab, 0);
            PLDG(bufB, Ab, 1);
            PSTS(bufA, st, 0);
            PLDG(bufA, Ab, 2);
            PSTS(bufB, st, 1);
            PLDG(bufB, Ab, 3);
            PSTS(bufA, st, 2);
            PSTS(bufB, st, 3);
            CP_WAIT0();
            MEMBAR_CTA();
            BAR_ARRIVE(1 + s);                   // publish stage full
        }
        return;
    }

    // ================= CONSUMERS (warps 0-7, 256 threads) ===================
    const int wid = tid >> 5, lane = tid & 31;
    const int wm = wid & 1, wn = wid >> 1;       // warp tile: m64 x n32

    const int a_r = (lane & 7) + ((lane >> 3) & 1) * 8;
    const uint32_t a_c16 = (uint32_t)(((lane >> 4) & 1) * 16);
    const uint32_t xf = (uint32_t)((a_r & 7) << 4);
    uint32_t colx[4];
    #pragma unroll
    for (int ks = 0; ks < 4; ks++) colx[ks] = (((uint32_t)ks << 5) | a_c16) ^ xf;

    float acc1[4][4][4] = {};   // P1 = Ah*Bh
    float acc2[4][4][4] = {};   // P2 = As*Bs
    int slot = cta * 2;

#define KSTEP(ks) do {                                                           \
    uint32_t ah[4][4], bh[2][4];                                                 \
    _Pragma("unroll")                                                            \
    for (int mf = 0; mf < 4; mf++)                                               \
        ldsm4(ah[mf], st + OFF_AH + (uint32_t)((wm * 64 + mf * 16 + a_r) * 128) + colx[ks]); \
    _Pragma("unroll")                                                            \
    for (int g = 0; g < 2; g++)                                                  \
        ldsm4(bh[g], st + OFF_BH + (uint32_t)((wn * 32 + g * 16 + a_r) * 128) + colx[ks]);   \
    _Pragma("unroll")                                                            \
    for (int mf = 0; mf < 4; mf++)                                               \
        _Pragma("unroll")                                                        \
        for (int g = 0; g < 2; g++) {                                            \
            mmaf16(acc1[mf][g * 2 + 0], ah[mf], bh[g][0], bh[g][2]);             \
            mmaf16(acc1[mf][g * 2 + 1], ah[mf], bh[g][1], bh[g][3]);             \
        }                                                                        \
    uint32_t as[4][4], bs[2][4];                                                 \
    _Pragma("unroll")                                                            \
    for (int mf = 0; mf < 4; mf++)                                               \
        ldsm4(as[mf], st + OFF_AS + (uint32_t)((wm * 64 + mf * 16 + a_r) * 128) + colx[ks]); \
    _Pragma("unroll")                                                            \
    for (int g = 0; g < 2; g++)                                                  \
        ldsm4(bs[g], st + OFF_BS + (uint32_t)((wn * 32 + g * 16 + a_r) * 128) + colx[ks]);   \
    _Pragma("unroll")                                                            \
    for (int mf = 0; mf < 4; mf++)                                               \
        _Pragma("unroll")                                                        \
        for (int g = 0; g < 2; g++) {                                            \
            mmaf16(acc2[mf][g * 2 + 0], as[mf], bs[g][0], bs[g][2]);             \
            mmaf16(acc2[mf][g * 2 + 1], as[mf], bs[g][1], bs[g][3]);             \
        } } while (0)

    for (int it = 0; it < total; it++) {
        const int s = it & 1;
        const uint32_t st = sbase + (uint32_t)(s * STAGE);
        BAR_SYNC(1 + s);                 // wait stage full
        KSTEP(0);
        KSTEP(1);
        KSTEP(2);
        KSTEP(3);
        if (it + 2 < total) BAR_ARRIVE(3 + s);   // signal stage empty

        const int u = u_begin + it;
        if (it == total - 1 || ((u + 1) & 1023) == 0) {
            // tile segment done: flush to slot, reset accumulators
            float* pb = g_partial + (size_t)slot * 16384;
            #pragma unroll
            for (int mf = 0; mf < 4; mf++)
                #pragma unroll
                for (int nf = 0; nf < 4; nf++) {
                    const int rl = wm * 64 + mf * 16 + (lane >> 2);
                    const int cl = wn * 32 + nf * 8 + (lane & 3) * 2;
                    const float v0 = fmaf(ONE_MK, acc1[mf][nf][0], acc2[mf][nf][0]);
                    const float v1 = fmaf(ONE_MK, acc1[mf][nf][1], acc2[mf][nf][1]);
                    const float v2 = fmaf(ONE_MK, acc1[mf][nf][2], acc2[mf][nf][2]);
                    const float v3 = fmaf(ONE_MK, acc1[mf][nf][3], acc2[mf][nf][3]);
                    *(float2*)(pb + rl * 128 + cl) = make_float2(v0, v1);
                    *(float2*)(pb + (rl + 8) * 128 + cl) = make_float2(v2, v3);
                    acc1[mf][nf][0] = acc1[mf][nf][1] = acc1[mf][nf][2] = acc1[mf][nf][3] = 0.f;
                    acc2[mf][nf][0] = acc2[mf][nf][1] = acc2[mf][nf][2] = acc2[mf][nf][3] = 0.f;
                }
            slot++;
        }
    }
}

// ---------------- fused: split-K reduce + bias/mask + student-t + argmax ----
__global__ __launch_bounds__(128) void cluster_kernel(const float* __restrict__ bias,
                                                      const int* __restrict__ mask,
                                                      const float* __restrict__ cent,
                                                      float* __restrict__ zall,
                                                      float* __restrict__ S,
                                                      float* __restrict__ Cidx) {
    const int tid = threadIdx.x;
    const int row0 = blockIdx.x * 8;
    __shared__ __align__(16) float zs[8][256];
    __shared__ float stmp[8][128];
    __shared__ float red_s[8];
    __shared__ int   red_i[8];
    __shared__ int   slots[2][8];
    __shared__ int   nslots[2];

    // contributor lists for this row-block's two mn-tiles
    if (tid == 0) {
        const int tbase = (row0 >> 7) << 1;
        #pragma unroll
        for (int h = 0; h < 2; h++) {
            const int t = tbase + h;
            int n = 0;
            int c0 = (t << 10) * NCTAS / TOTAL_UNITS - 1;
            if (c0 < 0) c0 = 0;
            for (int c = c0; c < c0 + 8 && c < NCTAS; c++) {
                const int u0 = (c * TOTAL_UNITS) / NCTAS;
                const int u1 = ((c + 1) * TOTAL_UNITS) / NCTAS;
                if (u0 < ((t + 1) << 10) && u1 > (t << 10))
                    slots[h][n++] = c * 2 + (((u0 >> 10) == t) ? 0 : 1);
            }
            nslots[h] = n;
        }
    }
    __syncthreads();

    // reduce: thread tid handles float2 column tid*2 across 8 rows
    {
        const int col = tid * 2;
        const int h = col >> 7;
        const int cl = col & 127;
        const int nct = nslots[h];
        const float bx = bias[col], by = bias[col + 1];
        #pragma unroll
        for (int r = 0; r < 8; r++) {
            const int row = row0 + r;
            const int rl = row & 127;
            float sx = 0.f, sy = 0.f;
            for (int i = 0; i < nct; i++) {
                const float2 v = *(const float2*)(g_partial +
                    (size_t)slots[h][i] * 16384 + rl * 128 + cl);
                sx += v.x; sy += v.y;
            }
            const float m = mask[row] ? 1.0f : 0.0f;
            sx = (sx + bx) * m;
            sy = (sy + by) * m;
            zs[r][col] = sx;
            zs[r][col + 1] = sy;
            *(float2*)&zall[(size_t)row * NDFv + col] = make_float2(sx, sy);
        }
    }
    __syncthreads();

    float v[8] = {0.f, 0.f, 0.f, 0.f, 0.f, 0.f, 0.f, 0.f};
    if (tid < NCv) {
        const float4* c4 = (const float4*)(cent + (size_t)tid * NDFv);
        float d[8] = {0.f, 0.f, 0.f, 0.f, 0.f, 0.f, 0.f, 0.f};
        #pragma unroll 2
        for (int j = 0; j < NDFv / 4; j++) {
            const float4 cv = c4[j];
            #pragma unroll
            for (int r = 0; r < 8; r++) {
                const float4 zv = ((const float4*)zs[r])[j];
                const float dx = zv.x - cv.x, dy = zv.y - cv.y;
                const float dz = zv.z - cv.z, dw = zv.w - cv.w;
                d[r] += dx * dx + dy * dy + dz * dz + dw * dw;
            }
        }
        #pragma unroll
        for (int r = 0; r < 8; r++)
            v[r] = 1.0f / (1.0f + sqrtf(fmaxf(d[r], 0.0f)));
    }
    #pragma unroll
    for (int r = 0; r < 8; r++) stmp[r][tid] = v[r];
    __syncthreads();

    #pragma unroll
    for (int pass = 0; pass < 2; pass++) {   // warp w reduces rows w and w+4
        const int r = (tid >> 5) + pass * 4;
        const int l = tid & 31;
        float sum = 0.0f, best = -1.0f;
        int bidx = 0;
        for (int k = l; k < NCv; k += 32) {
            const float x = stmp[r][k];
            sum += x;
            if (x > best) { best = x; bidx = k; }
        }
        #pragma unroll
        for (int off = 16; off > 0; off >>= 1) {
            sum += __shfl_down_sync(0xffffffffu, sum, off);
            const float ob = __shfl_down_sync(0xffffffffu, best, off);
            const int   oi = __shfl_down_sync(0xffffffffu, bidx, off);
            if (ob > best || (ob == best && oi < bidx)) { best = ob; bidx = oi; }
        }
        if (l == 0) { red_s[r] = sum; red_i[r] = bidx; }
    }
    __syncthreads();

    #pragma unroll
    for (int r = 0; r < 8; r++) {
        const int row = row0 + r;
        const bool m = mask[row] != 0;
        const float inv = m ? (1.0f / red_s[r]) : 0.0f;
        if (tid < NCv) S[(size_t)row * NCv + tid] = v[r] * inv;
        if (tid == 0)  Cidx[row] = m ? (float)red_i[r] : 0.0f;
    }
}

// ---------------------------------------------------------------------------
extern "C" void kernel_launch(void* const* d_in, const int* in_sizes, int n_in,
                              void* d_out, int out_size) {
    (void)in_sizes; (void)n_in; (void)out_size;
    const float* z_roi = (const float*)d_in[0];
    const int*   mask  = (const int*)d_in[1];
    const float* w_emb = (const float*)d_in[2];
    const float* b_emb = (const float*)d_in[3];
    const float* cent  = (const float*)d_in[4];

    float* out  = (float*)d_out;
    float* zall = out;
    float* S    = out + (size_t)MROWS * NDFv;
    float* Cx   = S + (size_t)MROWS * NCv;

    cudaFuncSetAttribute(gemm_mma_kernel, cudaFuncAttributeMaxDynamicSharedMemorySize, SMEM_TOTAL);

    bprep_kernel<<<dim3(KDIM / 32, NDFv / 32), 256>>>(w_emb);
    gemm_mma_kernel<<<NCTAS, NTHREADS, SMEM_TOTAL>>>(z_roi);
    cluster_kernel<<<MROWS / 8, 128>>>(b_emb, mask, cent, zall, S, Cx);
}

// round 16
// speedup vs baseline: 1.0109x; 1.0062x over previous
#include <cuda_runtime.h>
#include <cuda_fp16.h>
#include <cstdint>

#define KDIM   65536
#define MROWS  2048
#define NDFv   256
#define NCv    100
#define KC     64
#define NCTAS  148
#define TOTAL_UNITS 32768        // 32 mn-tiles * 1024 chunks
#define OFF_AH 0
#define OFF_AS 16384
#define OFF_BH 32768
#define OFF_BS 49152
#define STAGE  65536
#define SMEM_TOTAL (2 * STAGE)   // 128 KB

#define NTHREADS 320             // 256 consumers + 64 producers
#define KAPPA_INV 32.0f
#define ONE_MK    0.96875f       // 1 - 2^-5

// device-global scratch (no cudaMalloc allowed)
__device__ __align__(16) unsigned short g_Bh[(size_t)NDFv * KDIM]; // [n][k] fp16 rn(w)
__device__ __align__(16) unsigned short g_Bs[(size_t)NDFv * KDIM]; // [n][k] fp16 Bh+32*Bl
__device__ float g_partial[(size_t)2 * NCTAS * 16384];             // [cta*2+seg][128*128]

// ---------------- helpers (sm_80-class PTX only: valid on compute_103) ------
__device__ __forceinline__ uint32_t smem_u32(const void* p) {
    uint32_t a;
    asm("{ .reg .u64 t; cvta.to.shared.u64 t, %1; cvt.u32.u64 %0, t; }" : "=r"(a) : "l"(p));
    return a;
}
__device__ __forceinline__ uint32_t packh2(float lo, float hi) { // low half = rn16(lo)
    uint32_t r;
    asm("cvt.rn.f16x2.f32 %0, %1, %2;" : "=r"(r) : "f"(hi), "f"(lo));
    return r;
}
#define STS64V(a, r0, r1) \
    asm volatile("st.shared.v2.b32 [%0], {%1,%2};" :: "r"(a), "r"(r0), "r"(r1) : "memory")
#define CP_ASYNC16(dst, src) \
    asm volatile("cp.async.cg.shared.global [%0], [%1], 16;" :: "r"(dst), "l"(src) : "memory")
#define CP_COMMIT() asm volatile("cp.async.commit_group;" ::: "memory")
#define CP_WAIT0()  asm volatile("cp.async.wait_group 0;" ::: "memory")
#define MEMBAR_CTA() asm volatile("membar.cta;" ::: "memory")
#define BAR_SYNC(id)   asm volatile("bar.sync %0, %1;"   :: "r"(id), "r"(NTHREADS) : "memory")
#define BAR_ARRIVE(id) asm volatile("bar.arrive %0, %1;" :: "r"(id), "r"(NTHREADS) : "memory")
// barrier ids: 1+s = stage s FULL, 3+s = stage s EMPTY

__device__ __forceinline__ void ldsm4(uint32_t r[4], uint32_t a) {
    asm volatile("ldmatrix.sync.aligned.m8n8.x4.shared.b16 {%0,%1,%2,%3}, [%4];"
                 : "=r"(r[0]), "=r"(r[1]), "=r"(r[2]), "=r"(r[3]) : "r"(a));
}
__device__ __forceinline__ void mmaf16(float d[4], const uint32_t a[4],
                                       uint32_t b0, uint32_t b1) {
    asm volatile("mma.sync.aligned.m16n8k16.row.col.f32.f16.f16.f32 "
                 "{%0,%1,%2,%3},{%4,%5,%6,%7},{%8,%9},{%0,%1,%2,%3};"
                 : "+f"(d[0]), "+f"(d[1]), "+f"(d[2]), "+f"(d[3])
                 : "r"(a[0]), "r"(a[1]), "r"(a[2]), "r"(a[3]), "r"(b0), "r"(b1));
}

// ---------------- prepass: W [K,256] fp32 -> g_Bh/g_Bs [256][K] fp16 --------
// Packed uint32 (2 x fp16) stores; per-element math identical to scalar path.
__global__ __launch_bounds__(256) void bprep_kernel(const float* __restrict__ W) {
    __shared__ float tile[32][33];
    const int k0 = blockIdx.x * 32, n0 = blockIdx.y * 32;
    const int tx = threadIdx.x & 31, ty = threadIdx.x >> 5;
    #pragma unroll
    for (int i = 0; i < 4; i++)
        tile[ty * 4 + i][tx] = W[(size_t)(k0 + ty * 4 + i) * NDFv + n0 + tx];
    __syncthreads();
    const int kp = (tx & 15) * 2;        // k pair base
    const int nh = (tx >> 4) * 2;        // n subgroup (0 or 2)
    #pragma unroll
    for (int i2 = 0; i2 < 2; i2++) {
        const int nl = ty * 4 + nh + i2;
        const float w0 = tile[kp][nl];
        const float w1 = tile[kp + 1][nl];
        const uint32_t hp = packh2(w0, w1);
        const float bhf0 = __half2float(*(const __half*)&hp);
        const float bhf1 = __half2float(((const __half*)&hp)[1]);
        const uint32_t sp = packh2(fmaf(KAPPA_INV, w0 - bhf0, bhf0),
                                   fmaf(KAPPA_INV, w1 - bhf1, bhf1));
        const size_t idx = (size_t)(n0 + nl) * KDIM + k0 + kp;
        *(uint32_t*)&g_Bh[idx] = hp;
        *(uint32_t*)&g_Bs[idx] = sp;
    }
}

// ---------------- GEMM: fp16 2-pass kappa split, persistent balanced --------
__global__ __launch_bounds__(NTHREADS, 1) void gemm_mma_kernel(const float* __restrict__ A) {
    extern __shared__ char smem_dyn[];
    const uint32_t sbase = smem_u32(smem_dyn);
    const int tid = threadIdx.x;
    const int cta = blockIdx.x;
    const int u_begin = (cta * TOTAL_UNITS) / NCTAS;
    const int u_end   = ((cta + 1) * TOTAL_UNITS) / NCTAS;
    const int total   = u_end - u_begin;

    if (tid >= 256) {
        // ================= PRODUCER (warps 8-9, 64 threads) =================
        const int pt = tid - 256;             // 0..63
        const int prow = pt >> 4;             // A: row offset within group of 4
        const int pkf4 = pt & 15;             // A: float4 index within row
        const int prow8 = pt >> 3;            // B: row offset within group of 8
        const int pseg = pt & 7;              // B: 16B segment within row

        float4 bufA[8], bufB[8];

#define PLDG(buf, Ab, b) do {                                                    \
    _Pragma("unroll")                                                            \
    for (int j = 0; j < 8; j++) {                                                \
        const int row = (b) * 32 + j * 4 + prow;                                 \
        (buf)[j] = *(const float4*)((Ab) + (size_t)row * KDIM);                  \
    } } while (0)

#define PSTS(buf, st, b) do {                                                    \
    _Pragma("unroll")                                                            \
    for (int j = 0; j < 8; j++) {                                                \
        const int row = (b) * 32 + j * 4 + prow;                                 \
        const uint32_t off = (uint32_t)(row * 128) +                             \
                             (((uint32_t)(pkf4 * 8)) ^ ((uint32_t)((row & 7) << 4))); \
        const float4 f = (buf)[j];                                               \
        const uint32_t h0 = packh2(f.x, f.y);                                    \
        const uint32_t h1 = packh2(f.z, f.w);                                    \
        const float ahx = __half2float(*(const __half*)&h0);                     \
        const float ahy = __half2float(((const __half*)&h0)[1]);                 \
        const float ahz = __half2float(*(const __half*)&h1);                     \
        const float ahw = __half2float(((const __half*)&h1)[1]);                 \
        const uint32_t s0 = packh2(fmaf(-ONE_MK, ahx, f.x), fmaf(-ONE_MK, ahy, f.y)); \
        const uint32_t s1 = packh2(fmaf(-ONE_MK, ahz, f.z), fmaf(-ONE_MK, ahw, f.w)); \
        STS64V((st) + OFF_AH + off, h0, h1);                                     \
        STS64V((st) + OFF_AS + off, s0, s1);                                     \
    } } while (0)

        for (int it = 0; it < total; it++) {
            const int s = it & 1;
            const uint32_t st = sbase + (uint32_t)(s * STAGE);
            if (it >= 2) BAR_SYNC(3 + s);        // wait stage empty

            const int u  = u_begin + it;
            const int mt = u >> 11;              // tile>>1
            const int nt = (u >> 10) & 1;
            const int ch = u & 1023;

            // B -> cp.async (fills while we convert A)
            {
                const unsigned short* bh = g_Bh + (size_t)(nt * 128) * KDIM
                                           + (size_t)ch * KC + pseg * 8;
                const unsigned short* bs = g_Bs + (size_t)(nt * 128) * KDIM
                                           + (size_t)ch * KC + pseg * 8;
                #pragma unroll
                for (int j = 0; j < 16; j++) {
                    const int row = j * 8 + prow8;
                    const uint32_t off = (uint32_t)(row * 128) +
                        (((uint32_t)(pseg * 16)) ^ ((uint32_t)(prow8 << 4)));
                    CP_ASYNC16(st + OFF_BH + off, bh + (size_t)row * KDIM);
                    CP_ASYNC16(st + OFF_BS + off, bs + (size_t)row * KDIM);
                }
                CP_COMMIT();
            }
            // A: 4 batches, reg double-buffered
            const float* Ab = A + (size_t)(mt * 128) * KDIM + (size_t)ch * KC
                              + pkf4 * 4;
            PLDG(bufA, Ab, 0);
            PLDG(bufB, Ab, 1);
            PSTS(bufA, st, 0);
            PLDG(bufA, Ab, 2);
            PSTS(bufB, st, 1);
            PLDG(bufB, Ab, 3);
            PSTS(bufA, st, 2);
            PSTS(bufB, st, 3);
            CP_WAIT0();
            MEMBAR_CTA();
            BAR_ARRIVE(1 + s);                   // publish stage full
        }
        return;
    }

    // ================= CONSUMERS (warps 0-7, 256 threads) ===================
    const int wid = tid >> 5, lane = tid & 31;
    const int wm = wid & 1, wn = wid >> 1;       // warp tile: m64 x n32

    const int a_r = (lane & 7) + ((lane >> 3) & 1) * 8;
    const uint32_t a_c16 = (uint32_t)(((lane >> 4) & 1) * 16);
    const uint32_t xf = (uint32_t)((a_r & 7) << 4);
    uint32_t colx[4];
    #pragma unroll
    for (int ks = 0; ks < 4; ks++) colx[ks] = (((uint32_t)ks << 5) | a_c16) ^ xf;

    float acc1[4][4][4] = {};   // P1 = Ah*Bh
    float acc2[4][4][4] = {};   // P2 = As*Bs
    int slot = cta * 2;

#define KSTEP(ks) do {                                                           \
    uint32_t ah[4][4], bh[2][4];                                                 \
    _Pragma("unroll")                                                            \
    for (int mf = 0; mf < 4; mf++)                                               \
        ldsm4(ah[mf], st + OFF_AH + (uint32_t)((wm * 64 + mf * 16 + a_r) * 128) + colx[ks]); \
    _Pragma("unroll")                                                            \
    for (int g = 0; g < 2; g++)                                                  \
        ldsm4(bh[g], st + OFF_BH + (uint32_t)((wn * 32 + g * 16 + a_r) * 128) + colx[ks]);   \
    _Pragma("unroll")                                                            \
    for (int mf = 0; mf < 4; mf++)                                               \
        _Pragma("unroll")                                                        \
        for (int g = 0; g < 2; g++) {                                            \
            mmaf16(acc1[mf][g * 2 + 0], ah[mf], bh[g][0], bh[g][2]);             \
            mmaf16(acc1[mf][g * 2 + 1], ah[mf], bh[g][1], bh[g][3]);             \
        }                                                                        \
    uint32_t as[4][4], bs[2][4];                                                 \
    _Pragma("unroll")                                                            \
    for (int mf = 0; mf < 4; mf++)                                               \
        ldsm4(as[mf], st + OFF_AS + (uint32_t)((wm * 64 + mf * 16 + a_r) * 128) + colx[ks]); \
    _Pragma("unroll")                                                            \
    for (int g = 0; g < 2; g++)                                                  \
        ldsm4(bs[g], st + OFF_BS + (uint32_t)((wn * 32 + g * 16 + a_r) * 128) + colx[ks]);   \
    _Pragma("unroll")                                                            \
    for (int mf = 0; mf < 4; mf++)                                               \
        _Pragma("unroll")                                                        \
        for (int g = 0; g < 2; g++) {                                            \
            mmaf16(acc2[mf][g * 2 + 0], as[mf], bs[g][0], bs[g][2]);             \
            mmaf16(acc2[mf][g * 2 + 1], as[mf], bs[g][1], bs[g][3]);             \
        } } while (0)

    for (int it = 0; it < total; it++) {
        const int s = it & 1;
        const uint32_t st = sbase + (uint32_t)(s * STAGE);
        BAR_SYNC(1 + s);                 // wait stage full
        KSTEP(0);
        KSTEP(1);
        KSTEP(2);
        KSTEP(3);
        if (it + 2 < total) BAR_ARRIVE(3 + s);   // signal stage empty

        const int u = u_begin + it;
        if (it == total - 1 || ((u + 1) & 1023) == 0) {
            // tile segment done: flush to slot, reset accumulators
            float* pb = g_partial + (size_t)slot * 16384;
            #pragma unroll
            for (int mf = 0; mf < 4; mf++)
                #pragma unroll
                for (int nf = 0; nf < 4; nf++) {
                    const int rl = wm * 64 + mf * 16 + (lane >> 2);
                    const int cl = wn * 32 + nf * 8 + (lane & 3) * 2;
                    const float v0 = fmaf(ONE_MK, acc1[mf][nf][0], acc2[mf][nf][0]);
                    const float v1 = fmaf(ONE_MK, acc1[mf][nf][1], acc2[mf][nf][1]);
                    const float v2 = fmaf(ONE_MK, acc1[mf][nf][2], acc2[mf][nf][2]);
                    const float v3 = fmaf(ONE_MK, acc1[mf][nf][3], acc2[mf][nf][3]);
                    *(float2*)(pb + rl * 128 + cl) = make_float2(v0, v1);
                    *(float2*)(pb + (rl + 8) * 128 + cl) = make_float2(v2, v3);
                    acc1[mf][nf][0] = acc1[mf][nf][1] = acc1[mf][nf][2] = acc1[mf][nf][3] = 0.f;
                    acc2[mf][nf][0] = acc2[mf][nf][1] = acc2[mf][nf][2] = acc2[mf][nf][3] = 0.f;
                }
            slot++;
        }
    }
}

// ---------------- reduce: zall = (sum of contributing slots + bias) * mask --
__global__ __launch_bounds__(256) void reduce_kernel(const float* __restrict__ bias,
                                                     const int* __restrict__ mask,
                                                     float* __restrict__ zall) {
    const int i = blockIdx.x * 256 + threadIdx.x;   // float2 units
    const int row = i >> 7;
    const int col = (i & 127) * 2;
    const int t = ((row >> 7) << 1) | (col >> 7);   // mn-tile index 0..31
    const int rl = row & 127, cl = col & 127;

    float2 s = make_float2(0.f, 0.f);
    int c0 = (t << 10) * NCTAS / TOTAL_UNITS - 1;
    if (c0 < 0) c0 = 0;
    #pragma unroll 1
    for (int c = c0; c < c0 + 8; c++) {
        if (c >= NCTAS) break;
        const int u0 = (c * TOTAL_UNITS) / NCTAS;
        const int u1 = ((c + 1) * TOTAL_UNITS) / NCTAS;
        if (u0 < ((t + 1) << 10) && u1 > (t << 10)) {
            const int seg = ((u0 >> 10) == t) ? 0 : 1;
            const float2 v = *(const float2*)(g_partial +
                (size_t)(c * 2 + seg) * 16384 + rl * 128 + cl);
            s.x += v.x; s.y += v.y;
        }
    }
    const float m = mask[row] ? 1.0f : 0.0f;
    s.x = (s.x + bias[col]) * m;
    s.y = (s.y + bias[col + 1]) * m;
    *(float2*)&zall[(size_t)row * NDFv + col] = s;
}

// ---------------- student-t + normalize + argmax (8 rows, 256 threads) ------
// Threads 0-99 compute rows 0-3 (d[4] ILP); threads 128-227 rows 4-7.
// Per-(row,cluster) j-loop order identical to prior rounds -> bitwise same.
__global__ __launch_bounds__(256) void cluster_kernel(const float* __restrict__ Z,
                                                      const float* __restrict__ cent,
                                                      const int* __restrict__ mask,
                                                      float* __restrict__ S,
                                                      float* __restrict__ Cidx) {
    const int tid = threadIdx.x;
    const int row0 = blockIdx.x * 8;
    const int half = tid >> 7;           // 0: rows 0-3, 1: rows 4-7
    const int ht = tid & 127;            // thread within half (cluster index)
    __shared__ __align__(16) float zs[8][256];
    __shared__ float stmp[8][128];
    __shared__ float red_s[8];
    __shared__ int   red_i[8];

    #pragma unroll
    for (int i = 0; i < 8; i++) {
        const int idx = i * 256 + tid;
        zs[idx >> 8][idx & 255] = Z[(size_t)row0 * 256 + idx];
    }
    __syncthreads();

    float v[4] = {0.f, 0.f, 0.f, 0.f};
    if (ht < NCv) {
        const float4* c4 = (const float4*)(cent + (size_t)ht * NDFv);
        float d[4] = {0.f, 0.f, 0.f, 0.f};
        #pragma unroll 4
        for (int j = 0; j < NDFv / 4; j++) {
            const float4 cv = c4[j];
            #pragma unroll
            for (int r = 0; r < 4; r++) {
                const float4 zv = ((const float4*)zs[half * 4 + r])[j];
                const float dx = zv.x - cv.x, dy = zv.y - cv.y;
                const float dz = zv.z - cv.z, dw = zv.w - cv.w;
                d[r] += dx * dx + dy * dy + dz * dz + dw * dw;
            }
        }
        #pragma unroll
        for (int r = 0; r < 4; r++)
            v[r] = 1.0f / (1.0f + sqrtf(fmaxf(d[r], 0.0f)));
    }
    #pragma unroll
    for (int r = 0; r < 4; r++) stmp[half * 4 + r][ht] = v[r];
    __syncthreads();

    {   // 8 warps: warp w reduces row w
        const int r = tid >> 5, l = tid & 31;
        float sum = 0.0f, best = -1.0f;
        int bidx = 0;
        for (int k = l; k < NCv; k += 32) {
            const float x = stmp[r][k];
            sum += x;
            if (x > best) { best = x; bidx = k; }
        }
        #pragma unroll
        for (int off = 16; off > 0; off >>= 1) {
            sum += __shfl_down_sync(0xffffffffu, sum, off);
            const float ob = __shfl_down_sync(0xffffffffu, best, off);
            const int   oi = __shfl_down_sync(0xffffffffu, bidx, off);
            if (ob > best || (ob == best && oi < bidx)) { best = ob; bidx = oi; }
        }
        if (l == 0) { red_s[r] = sum; red_i[r] = bidx; }
    }
    __syncthreads();

    #pragma unroll
    for (int r = 0; r < 4; r++) {
        const int row = row0 + half * 4 + r;
        const bool m = mask[row] != 0;
        const float inv = m ? (1.0f / red_s[half * 4 + r]) : 0.0f;
        if (ht < NCv) S[(size_t)row * NCv + ht] = v[r] * inv;
        if (ht == 0)  Cidx[row] = m ? (float)red_i[half * 4 + r] : 0.0f;
    }
}

// ---------------------------------------------------------------------------
extern "C" void kernel_launch(void* const* d_in, const int* in_sizes, int n_in,
                              void* d_out, int out_size) {
    (void)in_sizes; (void)n_in; (void)out_size;
    const float* z_roi = (const float*)d_in[0];
    const int*   mask  = (const int*)d_in[1];
    const float* w_emb = (const float*)d_in[2];
    const float* b_emb = (const float*)d_in[3];
    const float* cent  = (const float*)d_in[4];

    float* out  = (float*)d_out;
    float* zall = out;
    float* S    = out + (size_t)MROWS * NDFv;
    float* Cx   = S + (size_t)MROWS * NCv;

    cudaFuncSetAttribute(gemm_mma_kernel, cudaFuncAttributeMaxDynamicSharedMemorySize, SMEM_TOTAL);

    bprep_kernel<<<dim3(KDIM / 32, NDFv / 32), 256>>>(w_emb);
    gemm_mma_kernel<<<NCTAS, NTHREADS, SMEM_TOTAL>>>(z_roi);
    reduce_kernel<<<(MROWS * NDFv / 2) / 256, 256>>>(b_emb, mask, zall);
    cluster_kernel<<<MROWS / 8, 256>>>(zall, cent, mask, S, Cx);
}

// round 17
// speedup vs baseline: 1.0262x; 1.0151x over previous
#include <cuda_runtime.h>
#include <cuda_fp16.h>
#include <cstdint>

#define KDIM   65536
#define MROWS  2048
#define NDFv   256
#define NCv    100
#define KC     64
#define NCTAS  148
#define TOTAL_UNITS 32768        // 32 mn-tiles * 1024 chunks
#define OFF_AH 0
#define OFF_AS 16384
#define OFF_BH 32768
#define OFF_BS 49152
#define STAGE  65536
#define SMEM_TOTAL (2 * STAGE)   // 128 KB

#define NTHREADS 320             // 256 consumers + 64 producers
#define KAPPA_INV 32.0f
#define ONE_MK    0.96875f       // 1 - 2^-5

// device-global scratch (no cudaMalloc allowed)
__device__ __align__(16) unsigned short g_Bh[(size_t)NDFv * KDIM]; // [n][k] fp16 rn(w)
__device__ __align__(16) unsigned short g_Bs[(size_t)NDFv * KDIM]; // [n][k] fp16 Bh+32*Bl
__device__ float g_partial[(size_t)2 * NCTAS * 16384];             // [cta*2+seg][128*128]

// ---------------- helpers (sm_80-class PTX only: valid on compute_103) ------
__device__ __forceinline__ uint32_t smem_u32(const void* p) {
    uint32_t a;
    asm("{ .reg .u64 t; cvta.to.shared.u64 t, %1; cvt.u32.u64 %0, t; }" : "=r"(a) : "l"(p));
    return a;
}
__device__ __forceinline__ uint32_t packh2(float lo, float hi) { // low half = rn16(lo)
    uint32_t r;
    asm("cvt.rn.f16x2.f32 %0, %1, %2;" : "=r"(r) : "f"(hi), "f"(lo));
    return r;
}
#define STS64V(a, r0, r1) \
    asm volatile("st.shared.v2.b32 [%0], {%1,%2};" :: "r"(a), "r"(r0), "r"(r1) : "memory")
#define CP_ASYNC16(dst, src) \
    asm volatile("cp.async.cg.shared.global [%0], [%1], 16;" :: "r"(dst), "l"(src) : "memory")
#define CP_COMMIT() asm volatile("cp.async.commit_group;" ::: "memory")
#define CP_WAIT0()  asm volatile("cp.async.wait_group 0;" ::: "memory")
#define MEMBAR_CTA() asm volatile("membar.cta;" ::: "memory")
#define BAR_SYNC(id)   asm volatile("bar.sync %0, %1;"   :: "r"(id), "r"(NTHREADS) : "memory")
#define BAR_ARRIVE(id) asm volatile("bar.arrive %0, %1;" :: "r"(id), "r"(NTHREADS) : "memory")
// barrier ids: 1+s = stage s FULL, 3+s = stage s EMPTY

__device__ __forceinline__ void ldsm4(uint32_t r[4], uint32_t a) {
    asm volatile("ldmatrix.sync.aligned.m8n8.x4.shared.b16 {%0,%1,%2,%3}, [%4];"
                 : "=r"(r[0]), "=r"(r[1]), "=r"(r[2]), "=r"(r[3]) : "r"(a));
}
__device__ __forceinline__ void mmaf16(float d[4], const uint32_t a[4],
                                       uint32_t b0, uint32_t b1) {
    asm volatile("mma.sync.aligned.m16n8k16.row.col.f32.f16.f16.f32 "
                 "{%0,%1,%2,%3},{%4,%5,%6,%7},{%8,%9},{%0,%1,%2,%3};"
                 : "+f"(d[0]), "+f"(d[1]), "+f"(d[2]), "+f"(d[3])
                 : "r"(a[0]), "r"(a[1]), "r"(a[2]), "r"(a[3]), "r"(b0), "r"(b1));
}

// ---------------- prepass: W [K,256] fp32 -> g_Bh/g_Bs [256][K] fp16 --------
// Packed uint32 (2 x fp16) stores; per-element math identical to scalar path.
__global__ __launch_bounds__(256) void bprep_kernel(const float* __restrict__ W) {
    __shared__ float tile[32][33];
    const int k0 = blockIdx.x * 32, n0 = blockIdx.y * 32;
    const int tx = threadIdx.x & 31, ty = threadIdx.x >> 5;
    #pragma unroll
    for (int i = 0; i < 4; i++)
        tile[ty * 4 + i][tx] = W[(size_t)(k0 + ty * 4 + i) * NDFv + n0 + tx];
    __syncthreads();
    const int kp = (tx & 15) * 2;        // k pair base
    const int nh = (tx >> 4) * 2;        // n subgroup (0 or 2)
    #pragma unroll
    for (int i2 = 0; i2 < 2; i2++) {
        const int nl = ty * 4 + nh + i2;
        const float w0 = tile[kp][nl];
        const float w1 = tile[kp + 1][nl];
        const uint32_t hp = packh2(w0, w1);
        const float bhf0 = __half2float(*(const __half*)&hp);
        const float bhf1 = __half2float(((const __half*)&hp)[1]);
        const uint32_t sp = packh2(fmaf(KAPPA_INV, w0 - bhf0, bhf0),
                                   fmaf(KAPPA_INV, w1 - bhf1, bhf1));
        const size_t idx = (size_t)(n0 + nl) * KDIM + k0 + kp;
        *(uint32_t*)&g_Bh[idx] = hp;
        *(uint32_t*)&g_Bs[idx] = sp;
    }
}

// ---------------- GEMM: fp16 2-pass kappa split, persistent balanced --------
__global__ __launch_bounds__(NTHREADS, 1) void gemm_mma_kernel(const float* __restrict__ A) {
    extern __shared__ char smem_dyn[];
    const uint32_t sbase = smem_u32(smem_dyn);
    const int tid = threadIdx.x;
    const int cta = blockIdx.x;
    const int u_begin = (cta * TOTAL_UNITS) / NCTAS;
    const int u_end   = ((cta + 1) * TOTAL_UNITS) / NCTAS;
    const int total   = u_end - u_begin;

    if (tid >= 256) {
        // ================= PRODUCER (warps 8-9, 64 threads) =================
        const int pt = tid - 256;             // 0..63
        const int prow = pt >> 4;             // A: row offset within group of 4
        const int pkf4 = pt & 15;             // A: float4 index within row
        const int prow8 = pt >> 3;            // B: row offset within group of 8
        const int pseg = pt & 7;              // B: 16B segment within row

        float4 bufA[8], bufB[8];

#define PLDG(buf, Ab, b) do {                                                    \
    _Pragma("unroll")                                                            \
    for (int j = 0; j < 8; j++) {                                                \
        const int row = (b) * 32 + j * 4 + prow;                                 \
        (buf)[j] = *(const float4*)((Ab) + (size_t)row * KDIM);                  \
    } } while (0)

#define PSTS(buf, st, b) do {                                                    \
    _Pragma("unroll")                                                            \
    for (int j = 0; j < 8; j++) {                                                \
        const int row = (b) * 32 + j * 4 + prow;                                 \
        const uint32_t off = (uint32_t)(row * 128) +                             \
                             (((uint32_t)(pkf4 * 8)) ^ ((uint32_t)((row & 7) << 4))); \
        const float4 f = (buf)[j];                                               \
        const uint32_t h0 = packh2(f.x, f.y);                                    \
        const uint32_t h1 = packh2(f.z, f.w);                                    \
        const float ahx = __half2float(*(const __half*)&h0);                     \
        const float ahy = __half2float(((const __half*)&h0)[1]);                 \
        const float ahz = __half2float(*(const __half*)&h1);                     \
        const float ahw = __half2float(((const __half*)&h1)[1]);                 \
        const uint32_t s0 = packh2(fmaf(-ONE_MK, ahx, f.x), fmaf(-ONE_MK, ahy, f.y)); \
        const uint32_t s1 = packh2(fmaf(-ONE_MK, ahz, f.z), fmaf(-ONE_MK, ahw, f.w)); \
        STS64V((st) + OFF_AH + off, h0, h1);                                     \
        STS64V((st) + OFF_AS + off, s0, s1);                                     \
    } } while (0)

        for (int it = 0; it < total; it++) {
            const int s = it & 1;
            const uint32_t st = sbase + (uint32_t)(s * STAGE);
            if (it >= 2) BAR_SYNC(3 + s);        // wait stage empty

            const int u  = u_begin + it;
            const int mt = u >> 11;              // tile>>1
            const int nt = (u >> 10) & 1;
            const int ch = u & 1023;

            // B -> cp.async (fills while we convert A)
            {
                const unsigned short* bh = g_Bh + (size_t)(nt * 128) * KDIM
                                           + (size_t)ch * KC + pseg * 8;
                const unsigned short* bs = g_Bs + (size_t)(nt * 128) * KDIM
                                           + (size_t)ch * KC + pseg * 8;
                #pragma unroll
                for (int j = 0; j < 16; j++) {
                    const int row = j * 8 + prow8;
                    const uint32_t off = (uint32_t)(row * 128) +
                        (((uint32_t)(pseg * 16)) ^ ((uint32_t)(prow8 << 4)));
                    CP_ASYNC16(st + OFF_BH + off, bh + (size_t)row * KDIM);
                    CP_ASYNC16(st + OFF_BS + off, bs + (size_t)row * KDIM);
                }
                CP_COMMIT();
            }
            // A: 4 batches, reg double-buffered
            const float* Ab = A + (size_t)(mt * 128) * KDIM + (size_t)ch * KC
                              + pkf4 * 4;
            PLDG(bufA, Ab, 0);
            PLDG(bufB, Ab, 1);
            PSTS(bufA, st, 0);
            PLDG(bufA, Ab, 2);
            PSTS(bufB, st, 1);
            PLDG(bufB, Ab, 3);
            PSTS(bufA, st, 2);
            PSTS(bufB, st, 3);
            CP_WAIT0();
            MEMBAR_CTA();
            BAR_ARRIVE(1 + s);                   // publish stage full
        }
        return;
    }

    // ================= CONSUMERS (warps 0-7, 256 threads) ===================
    const int wid = tid >> 5, lane = tid & 31;
    const int wm = wid & 1, wn = wid >> 1;       // warp tile: m64 x n32

    const int a_r = (lane & 7) + ((lane >> 3) & 1) * 8;
    const uint32_t a_c16 = (uint32_t)(((lane >> 4) & 1) * 16);
    const uint32_t xf = (uint32_t)((a_r & 7) << 4);
    uint32_t colx[4];
    #pragma unroll
    for (int ks = 0; ks < 4; ks++) colx[ks] = (((uint32_t)ks << 5) | a_c16) ^ xf;

    float acc1[4][4][4] = {};   // P1 = Ah*Bh
    float acc2[4][4][4] = {};   // P2 = As*Bs
    int slot = cta * 2;

#define KSTEP(ks) do {                                                           \
    uint32_t ah[4][4], bh[2][4];                                                 \
    _Pragma("unroll")                                                            \
    for (int mf = 0; mf < 4; mf++)                                               \
        ldsm4(ah[mf], st + OFF_AH + (uint32_t)((wm * 64 + mf * 16 + a_r) * 128) + colx[ks]); \
    _Pragma("unroll")                                                            \
    for (int g = 0; g < 2; g++)                                                  \
        ldsm4(bh[g], st + OFF_BH + (uint32_t)((wn * 32 + g * 16 + a_r) * 128) + colx[ks]);   \
    _Pragma("unroll")                                                            \
    for (int mf = 0; mf < 4; mf++)                                               \
        _Pragma("unroll")                                                        \
        for (int g = 0; g < 2; g++) {                                            \
            mmaf16(acc1[mf][g * 2 + 0], ah[mf], bh[g][0], bh[g][2]);             \
            mmaf16(acc1[mf][g * 2 + 1], ah[mf], bh[g][1], bh[g][3]);             \
        }                                                                        \
    uint32_t as[4][4], bs[2][4];                                                 \
    _Pragma("unroll")                                                            \
    for (int mf = 0; mf < 4; mf++)                                               \
        ldsm4(as[mf], st + OFF_AS + (uint32_t)((wm * 64 + mf * 16 + a_r) * 128) + colx[ks]); \
    _Pragma("unroll")                                                            \
    for (int g = 0; g < 2; g++)                                                  \
        ldsm4(bs[g], st + OFF_BS + (uint32_t)((wn * 32 + g * 16 + a_r) * 128) + colx[ks]);   \
    _Pragma("unroll")                                                            \
    for (int mf = 0; mf < 4; mf++)                                               \
        _Pragma("unroll")                                                        \
        for (int g = 0; g < 2; g++) {                                            \
            mmaf16(acc2[mf][g * 2 + 0], as[mf], bs[g][0], bs[g][2]);             \
            mmaf16(acc2[mf][g * 2 + 1], as[mf], bs[g][1], bs[g][3]);             \
        } } while (0)

    for (int it = 0; it < total; it++) {
        const int s = it & 1;
        const uint32_t st = sbase + (uint32_t)(s * STAGE);
        BAR_SYNC(1 + s);                 // wait stage full
        KSTEP(0);
        KSTEP(1);
        KSTEP(2);
        KSTEP(3);
        if (it + 2 < total) BAR_ARRIVE(3 + s);   // signal stage empty

        const int u = u_begin + it;
        if (it == total - 1 || ((u + 1) & 1023) == 0) {
            // tile segment done: flush to slot, reset accumulators
            float* pb = g_partial + (size_t)slot * 16384;
            #pragma unroll
            for (int mf = 0; mf < 4; mf++)
                #pragma unroll
                for (int nf = 0; nf < 4; nf++) {
                    const int rl = wm * 64 + mf * 16 + (lane >> 2);
                    const int cl = wn * 32 + nf * 8 + (lane & 3) * 2;
                    const float v0 = fmaf(ONE_MK, acc1[mf][nf][0], acc2[mf][nf][0]);
                    const float v1 = fmaf(ONE_MK, acc1[mf][nf][1], acc2[mf][nf][1]);
                    const float v2 = fmaf(ONE_MK, acc1[mf][nf][2], acc2[mf][nf][2]);
                    const float v3 = fmaf(ONE_MK, acc1[mf][nf][3], acc2[mf][nf][3]);
                    *(float2*)(pb + rl * 128 + cl) = make_float2(v0, v1);
                    *(float2*)(pb + (rl + 8) * 128 + cl) = make_float2(v2, v3);
                    acc1[mf][nf][0] = acc1[mf][nf][1] = acc1[mf][nf][2] = acc1[mf][nf][3] = 0.f;
                    acc2[mf][nf][0] = acc2[mf][nf][1] = acc2[mf][nf][2] = acc2[mf][nf][3] = 0.f;
                }
            slot++;
        }
    }
}

// ---------------- reduce: zall = (sum of contributing slots + bias) * mask --
__global__ __launch_bounds__(256) void reduce_kernel(const float* __restrict__ bias,
                                                     const int* __restrict__ mask,
                                                     float* __restrict__ zall) {
    const int i = blockIdx.x * 256 + threadIdx.x;   // float2 units
    const int row = i >> 7;
    const int col = (i & 127) * 2;
    const int t = ((row >> 7) << 1) | (col >> 7);   // mn-tile index 0..31
    const int rl = row & 127, cl = col & 127;

    float2 s = make_float2(0.f, 0.f);
    int c0 = (t << 10) * NCTAS / TOTAL_UNITS - 1;
    if (c0 < 0) c0 = 0;
    #pragma unroll 1
    for (int c = c0; c < c0 + 8; c++) {
        if (c >= NCTAS) break;
        const int u0 = (c * TOTAL_UNITS) / NCTAS;
        const int u1 = ((c + 1) * TOTAL_UNITS) / NCTAS;
        if (u0 < ((t + 1) << 10) && u1 > (t << 10)) {
            const int seg = ((u0 >> 10) == t) ? 0 : 1;
            const float2 v = *(const float2*)(g_partial +
                (size_t)(c * 2 + seg) * 16384 + rl * 128 + cl);
            s.x += v.x; s.y += v.y;
        }
    }
    const float m = mask[row] ? 1.0f : 0.0f;
    s.x = (s.x + bias[col]) * m;
    s.y = (s.y + bias[col + 1]) * m;
    *(float2*)&zall[(size_t)row * NDFv + col] = s;
}

// ---------------- student-t + normalize + argmax (8 rows / block, ILP x8) ---
__global__ __launch_bounds__(128) void cluster_kernel(const float* __restrict__ Z,
                                                      const float* __restrict__ cent,
                                                      const int* __restrict__ mask,
                                                      float* __restrict__ S,
                                                      float* __restrict__ Cidx) {
    const int tid = threadIdx.x;
    const int row0 = blockIdx.x * 8;
    __shared__ __align__(16) float zs[8][256];
    __shared__ float stmp[8][128];
    __shared__ float red_s[8];
    __shared__ int   red_i[8];

    #pragma unroll
    for (int i = 0; i < 16; i++) {
        const int idx = i * 128 + tid;
        zs[idx >> 8][idx & 255] = Z[(size_t)row0 * 256 + idx];
    }
    __syncthreads();

    float v[8] = {0.f, 0.f, 0.f, 0.f, 0.f, 0.f, 0.f, 0.f};
    if (tid < NCv) {
        const float4* c4 = (const float4*)(cent + (size_t)tid * NDFv);
        float d[8] = {0.f, 0.f, 0.f, 0.f, 0.f, 0.f, 0.f, 0.f};
        #pragma unroll 2
        for (int j = 0; j < NDFv / 4; j++) {
            const float4 cv = c4[j];
            #pragma unroll
            for (int r = 0; r < 8; r++) {
                const float4 zv = ((const float4*)zs[r])[j];
                const float dx = zv.x - cv.x, dy = zv.y - cv.y;
                const float dz = zv.z - cv.z, dw = zv.w - cv.w;
                d[r] += dx * dx + dy * dy + dz * dz + dw * dw;
            }
        }
        #pragma unroll
        for (int r = 0; r < 8; r++)
            v[r] = 1.0f / (1.0f + sqrtf(fmaxf(d[r], 0.0f)));
    }
    #pragma unroll
    for (int r = 0; r < 8; r++) stmp[r][tid] = v[r];
    __syncthreads();

    #pragma unroll
    for (int pass = 0; pass < 2; pass++) {   // warp w reduces rows w and w+4
        const int r = (tid >> 5) + pass * 4;
        const int l = tid & 31;
        float sum = 0.0f, best = -1.0f;
        int bidx = 0;
        for (int k = l; k < NCv; k += 32) {
            const float x = stmp[r][k];
            sum += x;
            if (x > best) { best = x; bidx = k; }
        }
        #pragma unroll
        for (int off = 16; off > 0; off >>= 1) {
            sum += __shfl_down_sync(0xffffffffu, sum, off);
            const float ob = __shfl_down_sync(0xffffffffu, best, off);
            const int   oi = __shfl_down_sync(0xffffffffu, bidx, off);
            if (ob > best || (ob == best && oi < bidx)) { best = ob; bidx = oi; }
        }
        if (l == 0) { red_s[r] = sum; red_i[r] = bidx; }
    }
    __syncthreads();

    #pragma unroll
    for (int r = 0; r < 8; r++) {
        const int row = row0 + r;
        const bool m = mask[row] != 0;
        const float inv = m ? (1.0f / red_s[r]) : 0.0f;
        if (tid < NCv) S[(size_t)row * NCv + tid] = v[r] * inv;
        if (tid == 0)  Cidx[row] = m ? (float)red_i[r] : 0.0f;
    }
}

// ---------------------------------------------------------------------------
extern "C" void kernel_launch(void* const* d_in, const int* in_sizes, int n_in,
                              void* d_out, int out_size) {
    (void)in_sizes; (void)n_in; (void)out_size;
    const float* z_roi = (const float*)d_in[0];
    const int*   mask  = (const int*)d_in[1];
    const float* w_emb = (const float*)d_in[2];
    const float* b_emb = (const float*)d_in[3];
    const float* cent  = (const float*)d_in[4];

    float* out  = (float*)d_out;
    float* zall = out;
    float* S    = out + (size_t)MROWS * NDFv;
    float* Cx   = S + (size_t)MROWS * NCv;

    cudaFuncSetAttribute(gemm_mma_kernel, cudaFuncAttributeMaxDynamicSharedMemorySize, SMEM_TOTAL);

    bprep_kernel<<<dim3(KDIM / 32, NDFv / 32), 256>>>(w_emb);
    gemm_mma_kernel<<<NCTAS, NTHREADS, SMEM_TOTAL>>>(z_roi);
    reduce_kernel<<<(MROWS * NDFv / 2) / 256, 256>>>(b_emb, mask, zall);
    cluster_kernel<<<MROWS / 8, 128>>>(zall, cent, mask, S, Cx);
}